// round 3
// baseline (speedup 1.0000x reference)
#include <cuda_runtime.h>

typedef unsigned long long u64;

#define NP 32768          // pixels = F*H*W = 2*128*128
#define SEQ 512           // window sequence length = F*16*16
#define NG 512            // head*window groups = 8*64

// ---------------- scratch (static __device__; no allocation APIs) ----------
__device__ float g_q [NG * 64 * SEQ];          // Q, d-major: [g][d][i]
__device__ float g_k [NG * 64 * SEQ];          // K, d-major: [g][d][j]
__device__ float g_v [NG * SEQ * 64];          // V: [g][j][d]
__device__ float g_ow[NG * SEQ * 64];          // attn out, window layout [g][i][d]
__device__ float g_op[512 * NP];               // attn out, pixel layout [ch][p]

// ---------------- packed fp32 helpers (Blackwell f32x2 pipe) ---------------
__device__ __forceinline__ u64 ffma2(u64 a, u64 b, u64 c) {
    u64 d;
    asm("fma.rn.f32x2 %0, %1, %2, %3;" : "=l"(d) : "l"(a), "l"(b), "l"(c));
    return d;
}
__device__ __forceinline__ u64 fmul2(u64 a, u64 b) {
    u64 d;
    asm("mul.rn.f32x2 %0, %1, %2;" : "=l"(d) : "l"(a), "l"(b));
    return d;
}
__device__ __forceinline__ float2 up2(u64 v) {
    float2 r;
    asm("mov.b64 {%0, %1}, %2;" : "=f"(r.x), "=f"(r.y) : "l"(v));
    return r;
}
__device__ __forceinline__ u64 dup2(float v) {
    u64 d;
    asm("mov.b64 %0, {%1, %1};" : "=l"(d) : "f"(v));
    return d;
}

// 8x8 micro-tile inner step: A = 4 packed pairs, W = 8 floats (dup'd to pairs)
#define MICRO_STEP(XsRow, WsRow)                                              \
    {                                                                         \
        ulonglong2 a0 = *(const ulonglong2*)&(XsRow)[ty * 8];                 \
        ulonglong2 a1 = *(const ulonglong2*)&(XsRow)[ty * 8 + 4];             \
        float4 w0 = *(const float4*)&(WsRow)[tx * 8];                         \
        float4 w1 = *(const float4*)&(WsRow)[tx * 8 + 4];                     \
        u64 A[4] = {a0.x, a0.y, a1.x, a1.y};                                  \
        u64 Wv[8] = {dup2(w0.x), dup2(w0.y), dup2(w0.z), dup2(w0.w),          \
                     dup2(w1.x), dup2(w1.y), dup2(w1.z), dup2(w1.w)};         \
        _Pragma("unroll")                                                     \
        for (int pp = 0; pp < 4; pp++) {                                      \
            _Pragma("unroll")                                                 \
            for (int oo = 0; oo < 8; oo++)                                    \
                acc[pp][oo] = ffma2(A[pp], Wv[oo], acc[pp][oo]);              \
        }                                                                     \
    }

// ============================================================================
// Kernel 1: QKV projection. out[o][p] = sum_c W[o][c] * x[c][p]
// Q,K stored d-major [g][d][i]; V stored [g][i][d].
// ============================================================================
__global__ void __launch_bounds__(256) proj_kernel(
    const float* __restrict__ x,
    const float* __restrict__ wq,
    const float* __restrict__ wkv)
{
    __shared__ __align__(16) float Xs[16][132];   // [c][p]
    __shared__ __align__(16) float Ws[16][132];   // [c][o]

    const int tid = threadIdx.x;
    const int tx = tid & 15, ty = tid >> 4;
    const int p0 = blockIdx.x * 128;
    const int o0 = blockIdx.y * 128;

    u64 acc[4][8];
    #pragma unroll
    for (int a = 0; a < 4; a++)
        #pragma unroll
        for (int b = 0; b < 8; b++) acc[a][b] = 0ull;

    for (int kt = 0; kt < 16; kt++) {
        const int c0 = kt * 16;
        #pragma unroll
        for (int q = 0; q < 2; q++) {
            int idx = q * 256 + tid;              // 0..511
            int xr = idx >> 5;                    // 0..15
            int xc = (idx & 31) * 4;
            *(float4*)&Xs[xr][xc] = *(const float4*)&x[(c0 + xr) * NP + p0 + xc];
            int orow = idx >> 2;                  // 0..127
            int cg   = (idx & 3) * 4;
            int o    = o0 + orow;
            const float* arow = (o < 512) ? (wq + o * 256) : (wkv + (o - 512) * 256);
            float4 w = *(const float4*)&arow[c0 + cg];
            Ws[cg + 0][orow] = w.x;
            Ws[cg + 1][orow] = w.y;
            Ws[cg + 2][orow] = w.z;
            Ws[cg + 3][orow] = w.w;
        }
        __syncthreads();
        #pragma unroll
        for (int kk = 0; kk < 16; kk++) MICRO_STEP(Xs[kk], Ws[kk]);
        __syncthreads();
    }

    // epilogue
    const int ob   = o0 + tx * 8;
    const int sel  = ob >> 9;        // 0=Q, 1=K, 2=V
    const int oc   = ob & 511;
    const int head = oc >> 6;
    const int dl   = oc & 63;

    // 8 consecutive p of this thread = 8 consecutive i in ONE window
    int p  = p0 + ty * 8;
    int f  = p >> 14;
    int hh = (p >> 7) & 127;
    int ww = p & 127;
    int win   = (hh >> 4) * 8 + (ww >> 4);
    int ibase = f * 256 + (hh & 15) * 16 + (ww & 15);
    int gidx  = head * 64 + win;

    if (sel < 2) {
        // d-major store: row = (gidx*64 + d), 8 consecutive i
        float* buf = sel ? g_k : g_q;
        #pragma unroll
        for (int oo = 0; oo < 8; oo++) {
            float2 q0 = up2(acc[0][oo]);
            float2 q1 = up2(acc[1][oo]);
            float2 q2 = up2(acc[2][oo]);
            float2 q3 = up2(acc[3][oo]);
            float* dst = &buf[(gidx * 64 + dl + oo) * 512 + ibase];
            *(float4*)&dst[0] = make_float4(q0.x, q0.y, q1.x, q1.y);
            *(float4*)&dst[4] = make_float4(q2.x, q2.y, q3.x, q3.y);
        }
    } else {
        // V: [g][i][d]
        #pragma unroll
        for (int pp = 0; pp < 4; pp++) {
            float2 r[8];
            #pragma unroll
            for (int oo = 0; oo < 8; oo++) r[oo] = up2(acc[pp][oo]);
            #pragma unroll
            for (int h = 0; h < 2; h++) {
                int irow = ibase + pp * 2 + h;
                float4 v0, v1;
                v0.x = h ? r[0].y : r[0].x;  v0.y = h ? r[1].y : r[1].x;
                v0.z = h ? r[2].y : r[2].x;  v0.w = h ? r[3].y : r[3].x;
                v1.x = h ? r[4].y : r[4].x;  v1.y = h ? r[5].y : r[5].x;
                v1.z = h ? r[6].y : r[6].x;  v1.w = h ? r[7].y : r[7].x;
                float* dst = &g_v[(gidx * 512 + irow) * 64 + dl];
                *(float4*)&dst[0] = v0;
                *(float4*)&dst[4] = v1;
            }
        }
    }
}

// ============================================================================
// Kernel 2: fused flash attention per (g, i-tile of 128).
// Streams j in chunks of 64: S = scale*Q@K^T (regs) -> online softmax ->
// P (SMEM) @ V accumulated in packed-f32x2 registers.
// Thread roles: ix = tid>>3 owns 4 i-rows (both phases);
// tj = tid&7 owns 8 j (QK) / 8 d (PV).
// ============================================================================
#define QS_STRIDE 132
#define KS_STRIDE 68
#define VS_STRIDE 72
#define PS_STRIDE 72
#define ATTN_SMEM ((64 * QS_STRIDE + 64 * KS_STRIDE + 64 * VS_STRIDE + 128 * PS_STRIDE) * 4)

__global__ void __launch_bounds__(256, 2) attn_kernel()
{
    extern __shared__ __align__(16) float smem[];
    float* Qs = smem;                                  // [64][132]  [d][i]
    float* Ks = Qs + 64 * QS_STRIDE;                   // [64][68]   [d][j]
    float* Vs = Ks + 64 * KS_STRIDE;                   // [64][72]   [j][d]
    float* Ps = Vs + 64 * VS_STRIDE;                   // [128][72]  [i][j]

    const int tid = threadIdx.x;
    const int tj = tid & 7;          // j-group (QK) / d-group (PV)
    const int ix = tid >> 3;         // i-group of 4
    const int g  = blockIdx.y;
    const int i0 = blockIdx.x * 128;

    const float* qbase = g_q + g * 64 * 512;    // [d][i]
    const float* kbase = g_k + g * 64 * 512;    // [d][j]
    const float* vbase = g_v + g * 512 * 64;    // [j][d]

    // load Q tile [64 d][128 i]
    #pragma unroll
    for (int q = 0; q < 8; q++) {
        int idx = q * 256 + tid;                // 0..2047
        int d  = idx >> 5;
        int ic = (idx & 31) * 4;
        *(float4*)&Qs[d * QS_STRIDE + ic] = *(const float4*)&qbase[d * 512 + i0 + ic];
    }

    float m[4] = {-1e30f, -1e30f, -1e30f, -1e30f};
    float l[4] = {0.f, 0.f, 0.f, 0.f};
    u64 oacc[4][4];
    #pragma unroll
    for (int a = 0; a < 4; a++)
        #pragma unroll
        for (int b = 0; b < 4; b++) oacc[a][b] = 0ull;

    for (int jc = 0; jc < 8; jc++) {
        const int j0 = jc * 64;
        // load K chunk [64 d][64 j] (already d-major in gmem)
        #pragma unroll
        for (int q = 0; q < 4; q++) {
            int idx = q * 256 + tid;            // 0..1023
            int d  = idx >> 4;
            int jq = (idx & 15) * 4;
            *(float4*)&Ks[d * KS_STRIDE + jq] = *(const float4*)&kbase[d * 512 + j0 + jq];
        }
        // load V chunk [64 j][64 d]
        #pragma unroll
        for (int q = 0; q < 4; q++) {
            int idx = q * 256 + tid;
            int j  = idx >> 4;
            int dq = (idx & 15) * 4;
            *(float4*)&Vs[j * VS_STRIDE + dq] = *(const float4*)&vbase[(j0 + j) * 64 + dq];
        }
        __syncthreads();

        // ---- QK: S[8 j (packed pairs)][4 i] ----
        u64 sacc[4][4];
        #pragma unroll
        for (int a = 0; a < 4; a++)
            #pragma unroll
            for (int b = 0; b < 4; b++) sacc[a][b] = 0ull;

        #pragma unroll 4
        for (int d = 0; d < 64; d++) {
            ulonglong2 k0 = *(const ulonglong2*)&Ks[d * KS_STRIDE + tj * 8];
            ulonglong2 k1 = *(const ulonglong2*)&Ks[d * KS_STRIDE + tj * 8 + 4];
            float4 qv = *(const float4*)&Qs[d * QS_STRIDE + ix * 4];
            u64 A[4] = {k0.x, k0.y, k1.x, k1.y};
            u64 W[4] = {dup2(qv.x), dup2(qv.y), dup2(qv.z), dup2(qv.w)};
            #pragma unroll
            for (int jp = 0; jp < 4; jp++)
                #pragma unroll
                for (int ii = 0; ii < 4; ii++)
                    sacc[jp][ii] = ffma2(A[jp], W[ii], sacc[jp][ii]);
        }

        // ---- online softmax + P store ----
        const float scale = 0.125f;
        #pragma unroll
        for (int ii = 0; ii < 4; ii++) {
            float e[8];
            #pragma unroll
            for (int jp = 0; jp < 4; jp++) {
                float2 s2 = up2(sacc[jp][ii]);
                e[jp * 2]     = s2.x * scale;
                e[jp * 2 + 1] = s2.y * scale;
            }
            float mx = e[0];
            #pragma unroll
            for (int t = 1; t < 8; t++) mx = fmaxf(mx, e[t]);
            mx = fmaxf(mx, __shfl_xor_sync(0xffffffffu, mx, 1));
            mx = fmaxf(mx, __shfl_xor_sync(0xffffffffu, mx, 2));
            mx = fmaxf(mx, __shfl_xor_sync(0xffffffffu, mx, 4));
            float mnew = fmaxf(m[ii], mx);
            float corr = __expf(m[ii] - mnew);
            m[ii] = mnew;
            float sum = 0.f;
            #pragma unroll
            for (int t = 0; t < 8; t++) { e[t] = __expf(e[t] - mnew); sum += e[t]; }
            sum += __shfl_xor_sync(0xffffffffu, sum, 1);
            sum += __shfl_xor_sync(0xffffffffu, sum, 2);
            sum += __shfl_xor_sync(0xffffffffu, sum, 4);
            l[ii] = l[ii] * corr + sum;
            u64 c2 = dup2(corr);
            #pragma unroll
            for (int dp = 0; dp < 4; dp++) oacc[ii][dp] = fmul2(oacc[ii][dp], c2);
            float* pr = &Ps[(ix * 4 + ii) * PS_STRIDE + tj * 8];
            *(float4*)&pr[0] = make_float4(e[0], e[1], e[2], e[3]);
            *(float4*)&pr[4] = make_float4(e[4], e[5], e[6], e[7]);
        }
        __syncthreads();

        // ---- PV: O[4 i][8 d packed] += P @ V ----
        #pragma unroll 2
        for (int j = 0; j < 64; j += 2) {
            ulonglong2 va = *(const ulonglong2*)&Vs[j * VS_STRIDE + tj * 8];
            ulonglong2 vb = *(const ulonglong2*)&Vs[j * VS_STRIDE + tj * 8 + 4];
            ulonglong2 wa = *(const ulonglong2*)&Vs[(j + 1) * VS_STRIDE + tj * 8];
            ulonglong2 wb = *(const ulonglong2*)&Vs[(j + 1) * VS_STRIDE + tj * 8 + 4];
            u64 V0[4] = {va.x, va.y, vb.x, vb.y};
            u64 V1[4] = {wa.x, wa.y, wb.x, wb.y};
            #pragma unroll
            for (int ii = 0; ii < 4; ii++) {
                float2 p2 = *(const float2*)&Ps[(ix * 4 + ii) * PS_STRIDE + j];
                u64 pa = dup2(p2.x), pb = dup2(p2.y);
                #pragma unroll
                for (int dp = 0; dp < 4; dp++)
                    oacc[ii][dp] = ffma2(V0[dp], pa, ffma2(V1[dp], pb, oacc[ii][dp]));
            }
        }
        __syncthreads();
    }

    // ---- epilogue: O / l -> g_ow [g][i][d] ----
    #pragma unroll
    for (int ii = 0; ii < 4; ii++) {
        float rl = __fdividef(1.0f, l[ii]);
        float2 r0 = up2(oacc[ii][0]);
        float2 r1 = up2(oacc[ii][1]);
        float2 r2 = up2(oacc[ii][2]);
        float2 r3 = up2(oacc[ii][3]);
        int irow = i0 + ix * 4 + ii;
        float* dst = &g_ow[(g * 512 + irow) * 64 + tj * 8];
        *(float4*)&dst[0] = make_float4(r0.x * rl, r0.y * rl, r1.x * rl, r1.y * rl);
        *(float4*)&dst[4] = make_float4(r2.x * rl, r2.y * rl, r3.x * rl, r3.y * rl);
    }
}

// ============================================================================
// Kernel 3: window layout [g][i][d] -> pixel layout [ch][p] via SMEM staging.
// ============================================================================
__global__ void __launch_bounds__(256) transpose_kernel()
{
    __shared__ __align__(16) float T[128][68];

    const int tid = threadIdx.x;
    const int g  = blockIdx.y;
    const int i0 = blockIdx.x * 128;
    const float* src = g_ow + (g * 512 + i0) * 64;

    #pragma unroll
    for (int q = 0; q < 8; q++) {
        int idx = q * 256 + tid;       // 0..2047
        int row = idx >> 4;            // 0..127
        int d4  = (idx & 15) * 4;
        *(float4*)&T[row][d4] = *(const float4*)&src[row * 64 + d4];
    }
    __syncthreads();

    const int head = g >> 6;
    const int win  = g & 63;
    const int wxv  = win >> 3, wyv = win & 7;

    #pragma unroll
    for (int q = 0; q < 2; q++) {
        int t   = q * 256 + tid;       // 0..511
        int d   = t & 63;
        int run = t >> 6;              // 0..7
        int ib  = run * 16;
        int ig  = i0 + ib;
        int f   = ig >> 8;
        int w1  = (ig >> 4) & 15;
        int pbase = f * 16384 + (wxv * 16 + w1) * 128 + wyv * 16;
        float* dst = g_op + (head * 64 + d) * NP + pbase;
        #pragma unroll
        for (int e = 0; e < 4; e++) {
            float4 v4;
            v4.x = T[ib + e * 4 + 0][d];
            v4.y = T[ib + e * 4 + 1][d];
            v4.z = T[ib + e * 4 + 2][d];
            v4.w = T[ib + e * 4 + 3][d];
            *(float4*)&dst[e * 4] = v4;
        }
    }
}

// ============================================================================
// Kernel 4: final projection + bias. Block 128p x 128o, 256 threads.
// ============================================================================
__global__ void __launch_bounds__(256) out_kernel(
    const float* __restrict__ wo,
    const float* __restrict__ bo,
    float* __restrict__ out)
{
    __shared__ __align__(16) float Bs[16][132];   // [c][p]
    __shared__ __align__(16) float Ws[16][132];   // [c][o]

    const int tid = threadIdx.x;
    const int tx = tid & 15, ty = tid >> 4;
    const int p0 = blockIdx.x * 128;
    const int o0 = blockIdx.y * 128;

    u64 acc[4][8];
    #pragma unroll
    for (int a = 0; a < 4; a++)
        #pragma unroll
        for (int b = 0; b < 8; b++) acc[a][b] = 0ull;

    for (int kt = 0; kt < 32; kt++) {
        const int c0 = kt * 16;
        #pragma unroll
        for (int q = 0; q < 2; q++) {
            int idx = q * 256 + tid;
            int xr = idx >> 5;
            int xc = (idx & 31) * 4;
            *(float4*)&Bs[xr][xc] = *(const float4*)&g_op[(c0 + xr) * NP + p0 + xc];
            int orow = idx >> 2;
            int cg   = (idx & 3) * 4;
            float4 w = *(const float4*)&wo[(o0 + orow) * 512 + c0 + cg];
            Ws[cg + 0][orow] = w.x;
            Ws[cg + 1][orow] = w.y;
            Ws[cg + 2][orow] = w.z;
            Ws[cg + 3][orow] = w.w;
        }
        __syncthreads();
        #pragma unroll
        for (int kk = 0; kk < 16; kk++) MICRO_STEP(Bs[kk], Ws[kk]);
        __syncthreads();
    }

    #pragma unroll
    for (int oo = 0; oo < 8; oo++) {
        int o_ = o0 + tx * 8 + oo;
        float b = bo[o_];
        float2 r0 = up2(acc[0][oo]);
        float2 r1 = up2(acc[1][oo]);
        float2 r2 = up2(acc[2][oo]);
        float2 r3 = up2(acc[3][oo]);
        float* dst = &out[o_ * NP + p0 + ty * 8];
        *(float4*)&dst[0] = make_float4(r0.x + b, r0.y + b, r1.x + b, r1.y + b);
        *(float4*)&dst[4] = make_float4(r2.x + b, r2.y + b, r3.x + b, r3.y + b);
    }
}

// ============================================================================
extern "C" void kernel_launch(void* const* d_in, const int* in_sizes, int n_in,
                              void* d_out, int out_size)
{
    const float* x   = (const float*)d_in[0];
    const float* wq  = (const float*)d_in[1];
    const float* wkv = (const float*)d_in[2];
    const float* wo  = (const float*)d_in[3];
    const float* bo  = (const float*)d_in[4];
    float* out = (float*)d_out;

    cudaFuncSetAttribute(attn_kernel,
                         cudaFuncAttributeMaxDynamicSharedMemorySize, ATTN_SMEM);

    proj_kernel     <<<dim3(NP / 128, 1536 / 128), 256>>>(x, wq, wkv);
    attn_kernel     <<<dim3(4, NG),                256, ATTN_SMEM>>>();
    transpose_kernel<<<dim3(4, NG),                256>>>();
    out_kernel      <<<dim3(NP / 128, 256 / 128),  256>>>(wo, bo, out);
}

// round 4
// speedup vs baseline: 1.1664x; 1.1664x over previous
#include <cuda_runtime.h>

#define NP 32768          // pixels = F*H*W = 2*128*128
#define SEQ 512           // window sequence length
#define NG 512            // head*window groups = 8*64

// ---------------- scratch (static __device__; no allocation APIs) ----------
__device__ float g_q [NG * SEQ * 64];          // [g][i][d]
__device__ float g_k [NG * SEQ * 64];          // [g][j][d]
__device__ float g_v [NG * SEQ * 64];          // [g][j][d]
__device__ float g_s [NG * SEQ * SEQ];         // [g][i][j]
__device__ float g_ow[NG * SEQ * 64];          // attn out, window layout
__device__ float g_op[512 * NP];               // attn out, pixel layout [ch][p]

// ---------------- tf32 helpers ---------------------------------------------
__device__ __forceinline__ float totf32(float x) {
    float r; asm("cvt.rna.tf32.f32 %0, %1;" : "=f"(r) : "f"(x)); return r;
}
__device__ __forceinline__ void split1(float v, float& h, float& l) {
    h = totf32(v); l = totf32(v - h);
}
__device__ __forceinline__ void mma_tf32(float* d, const unsigned* a, const unsigned* b) {
    asm("mma.sync.aligned.m16n8k8.row.col.f32.tf32.tf32.f32 "
        "{%0,%1,%2,%3}, {%4,%5,%6,%7}, {%8,%9}, {%0,%1,%2,%3};"
        : "+f"(d[0]), "+f"(d[1]), "+f"(d[2]), "+f"(d[3])
        : "r"(a[0]), "r"(a[1]), "r"(a[2]), "r"(a[3]), "r"(b[0]), "r"(b[1]));
}

// tf32x3 compute over one k=16 SMEM chunk.
// A: [k][M] tiles (hi/lo), B: [k][N] tiles (hi/lo). Warp tile 64(M) x 32(N).
// Needs in scope: g, tig, wm, wn, float acc[4][4][4].
#define MMA3_CHUNK(AH, AL, SA, BH, BL, SB)                                    \
    _Pragma("unroll")                                                         \
    for (int ks = 0; ks < 2; ks++) {                                          \
        const int k0 = ks * 8;                                                \
        unsigned ah[4][4], al[4][4];                                          \
        _Pragma("unroll")                                                     \
        for (int mt = 0; mt < 4; mt++) {                                      \
            const float* aph = &(AH)[(k0 + tig) * (SA) + wm + mt * 16 + g];   \
            const float* apl = &(AL)[(k0 + tig) * (SA) + wm + mt * 16 + g];   \
            ah[mt][0] = __float_as_uint(aph[0]);                              \
            ah[mt][1] = __float_as_uint(aph[8]);                              \
            ah[mt][2] = __float_as_uint(aph[4 * (SA)]);                       \
            ah[mt][3] = __float_as_uint(aph[4 * (SA) + 8]);                   \
            al[mt][0] = __float_as_uint(apl[0]);                              \
            al[mt][1] = __float_as_uint(apl[8]);                              \
            al[mt][2] = __float_as_uint(apl[4 * (SA)]);                       \
            al[mt][3] = __float_as_uint(apl[4 * (SA) + 8]);                   \
        }                                                                     \
        _Pragma("unroll")                                                     \
        for (int nt = 0; nt < 4; nt++) {                                      \
            const float* bph = &(BH)[(k0 + tig) * (SB) + wn + nt * 8 + g];    \
            const float* bpl = &(BL)[(k0 + tig) * (SB) + wn + nt * 8 + g];    \
            unsigned bh[2], bl[2];                                            \
            bh[0] = __float_as_uint(bph[0]);                                  \
            bh[1] = __float_as_uint(bph[4 * (SB)]);                           \
            bl[0] = __float_as_uint(bpl[0]);                                  \
            bl[1] = __float_as_uint(bpl[4 * (SB)]);                           \
            _Pragma("unroll")                                                 \
            for (int mt = 0; mt < 4; mt++) {                                  \
                mma_tf32(acc[mt][nt], al[mt], bh);                            \
                mma_tf32(acc[mt][nt], ah[mt], bl);                            \
                mma_tf32(acc[mt][nt], ah[mt], bh);                            \
            }                                                                 \
        }                                                                     \
    }

// ============================================================================
// Kernel 1: QKV projection. out[o][p] = sum_c W[o][c] * x[c][p]
// Block 128p(M) x 128o(N). Scatter to [g][i][d] layouts.
// ============================================================================
__global__ void __launch_bounds__(256) proj_kernel(
    const float* __restrict__ x,
    const float* __restrict__ wq,
    const float* __restrict__ wkv)
{
    __shared__ __align__(16) float XsH[16][132], XsL[16][132];   // [c][p]
    __shared__ __align__(16) float WsH[16][132], WsL[16][132];   // [c][o]

    const int tid  = threadIdx.x;
    const int lane = tid & 31, warp = tid >> 5;
    const int g = lane >> 2, tig = lane & 3;
    const int wm = (warp >> 2) * 64;       // p
    const int wn = (warp & 3) * 32;        // o
    const int p0 = blockIdx.x * 128;
    const int o0 = blockIdx.y * 128;

    float acc[4][4][4];
    #pragma unroll
    for (int a = 0; a < 4; a++)
        #pragma unroll
        for (int b = 0; b < 4; b++)
            #pragma unroll
            for (int c = 0; c < 4; c++) acc[a][b][c] = 0.f;

    for (int kt = 0; kt < 16; kt++) {
        const int c0 = kt * 16;
        #pragma unroll
        for (int q = 0; q < 2; q++) {
            int idx = q * 256 + tid;              // 0..511
            int xr = idx >> 5;                    // 0..15
            int xc = (idx & 31) * 4;
            float4 xv = *(const float4*)&x[(c0 + xr) * NP + p0 + xc];
            float4 xh, xl;
            split1(xv.x, xh.x, xl.x); split1(xv.y, xh.y, xl.y);
            split1(xv.z, xh.z, xl.z); split1(xv.w, xh.w, xl.w);
            *(float4*)&XsH[xr][xc] = xh;
            *(float4*)&XsL[xr][xc] = xl;

            int orow = idx >> 2;                  // 0..127
            int cg   = (idx & 3) * 4;
            int o    = o0 + orow;
            const float* arow = (o < 512) ? (wq + o * 256) : (wkv + (o - 512) * 256);
            float4 w = *(const float4*)&arow[c0 + cg];
            float h, l;
            split1(w.x, h, l); WsH[cg + 0][orow] = h; WsL[cg + 0][orow] = l;
            split1(w.y, h, l); WsH[cg + 1][orow] = h; WsL[cg + 1][orow] = l;
            split1(w.z, h, l); WsH[cg + 2][orow] = h; WsL[cg + 2][orow] = l;
            split1(w.w, h, l); WsH[cg + 3][orow] = h; WsL[cg + 3][orow] = l;
        }
        __syncthreads();
        MMA3_CHUNK(&XsH[0][0], &XsL[0][0], 132, &WsH[0][0], &WsL[0][0], 132);
        __syncthreads();
    }

    // epilogue: D[m=p][n=o] fragments -> float2 along d
    #pragma unroll
    for (int nt = 0; nt < 4; nt++) {
        int o   = o0 + wn + nt * 8 + 2 * tig;
        int sel = o >> 9;
        int oc  = o & 511;
        float* buf = (sel == 0) ? g_q : ((sel == 1) ? g_k : g_v);
        int gd = (oc >> 6) * 64;   // head*64
        int dl = oc & 63;
        #pragma unroll
        for (int mt = 0; mt < 4; mt++) {
            #pragma unroll
            for (int r = 0; r < 2; r++) {
                int p  = p0 + wm + mt * 16 + g + r * 8;
                int f  = p >> 14, hh = (p >> 7) & 127, ww = p & 127;
                int gidx = gd + (hh >> 4) * 8 + (ww >> 4);
                int i    = f * 256 + (hh & 15) * 16 + (ww & 15);
                *(float2*)&buf[(gidx * 512 + i) * 64 + dl] =
                    make_float2(acc[mt][nt][r * 2], acc[mt][nt][r * 2 + 1]);
            }
        }
    }
}

// ============================================================================
// Kernel 2: S = scale * Q @ K^T per group. Block 128i(M) x 128j(N).
// ============================================================================
__global__ void __launch_bounds__(256) qk_kernel()
{
    __shared__ __align__(16) float QsH[16][132], QsL[16][132];   // [d][i]
    __shared__ __align__(16) float KsH[16][132], KsL[16][132];   // [d][j]

    const int tid  = threadIdx.x;
    const int lane = tid & 31, warp = tid >> 5;
    const int g = lane >> 2, tig = lane & 3;
    const int wm = (warp >> 2) * 64;       // i
    const int wn = (warp & 3) * 32;        // j
    const int gz = blockIdx.z;
    const int i0 = blockIdx.y * 128;
    const int j0 = blockIdx.x * 128;
    const float* qbase = g_q + gz * SEQ * 64;
    const float* kbase = g_k + gz * SEQ * 64;

    float acc[4][4][4];
    #pragma unroll
    for (int a = 0; a < 4; a++)
        #pragma unroll
        for (int b = 0; b < 4; b++)
            #pragma unroll
            for (int c = 0; c < 4; c++) acc[a][b][c] = 0.f;

    for (int dcb = 0; dcb < 4; dcb++) {
        const int dc = dcb * 16;
        #pragma unroll
        for (int q = 0; q < 2; q++) {
            int idx = q * 256 + tid;              // 0..511
            int row = idx >> 2;                   // 0..127
            int dg  = (idx & 3) * 4;
            float4 qv = *(const float4*)&qbase[(i0 + row) * 64 + dc + dg];
            float h, l;
            split1(qv.x, h, l); QsH[dg + 0][row] = h; QsL[dg + 0][row] = l;
            split1(qv.y, h, l); QsH[dg + 1][row] = h; QsL[dg + 1][row] = l;
            split1(qv.z, h, l); QsH[dg + 2][row] = h; QsL[dg + 2][row] = l;
            split1(qv.w, h, l); QsH[dg + 3][row] = h; QsL[dg + 3][row] = l;
            float4 kv = *(const float4*)&kbase[(j0 + row) * 64 + dc + dg];
            split1(kv.x, h, l); KsH[dg + 0][row] = h; KsL[dg + 0][row] = l;
            split1(kv.y, h, l); KsH[dg + 1][row] = h; KsL[dg + 1][row] = l;
            split1(kv.z, h, l); KsH[dg + 2][row] = h; KsL[dg + 2][row] = l;
            split1(kv.w, h, l); KsH[dg + 3][row] = h; KsL[dg + 3][row] = l;
        }
        __syncthreads();
        MMA3_CHUNK(&QsH[0][0], &QsL[0][0], 132, &KsH[0][0], &KsL[0][0], 132);
        __syncthreads();
    }

    const float scale = 0.125f;
    #pragma unroll
    for (int mt = 0; mt < 4; mt++) {
        #pragma unroll
        for (int r = 0; r < 2; r++) {
            int i = i0 + wm + mt * 16 + g + r * 8;
            float* srow = &g_s[(gz * 512 + i) * 512 + j0];
            #pragma unroll
            for (int nt = 0; nt < 4; nt++) {
                int jj = wn + nt * 8 + 2 * tig;
                *(float2*)&srow[jj] = make_float2(acc[mt][nt][r * 2] * scale,
                                                  acc[mt][nt][r * 2 + 1] * scale);
            }
        }
    }
}

// ============================================================================
// Kernel 3: row softmax over j (512). One warp per row.
// ============================================================================
__global__ void __launch_bounds__(256) softmax_kernel()
{
    const int warp = threadIdx.x >> 5;
    const int lane = threadIdx.x & 31;
    const long long row = (long long)blockIdx.x * 8 + warp;
    float* rp = g_s + row * 512;

    float4 v[4];
    #pragma unroll
    for (int c = 0; c < 4; c++) v[c] = *(const float4*)&rp[c * 128 + lane * 4];

    float m = -1e30f;
    #pragma unroll
    for (int c = 0; c < 4; c++)
        m = fmaxf(m, fmaxf(fmaxf(v[c].x, v[c].y), fmaxf(v[c].z, v[c].w)));
    #pragma unroll
    for (int s = 16; s > 0; s >>= 1)
        m = fmaxf(m, __shfl_xor_sync(0xffffffffu, m, s));

    float sum = 0.f;
    #pragma unroll
    for (int c = 0; c < 4; c++) {
        v[c].x = __expf(v[c].x - m); v[c].y = __expf(v[c].y - m);
        v[c].z = __expf(v[c].z - m); v[c].w = __expf(v[c].w - m);
        sum += v[c].x + v[c].y + v[c].z + v[c].w;
    }
    #pragma unroll
    for (int s = 16; s > 0; s >>= 1)
        sum += __shfl_xor_sync(0xffffffffu, sum, s);

    const float inv = 1.0f / sum;
    #pragma unroll
    for (int c = 0; c < 4; c++) {
        v[c].x *= inv; v[c].y *= inv; v[c].z *= inv; v[c].w *= inv;
        *(float4*)&rp[c * 128 + lane * 4] = v[c];
    }
}

// ============================================================================
// Kernel 4: O = P @ V per group. Block 128i(M) x 64d(N), 128 threads.
// ============================================================================
__global__ void __launch_bounds__(128) pv_kernel()
{
    __shared__ __align__(16) float PsH[16][132], PsL[16][132];   // [j][i]
    __shared__ __align__(16) float VsH[16][68],  VsL[16][68];    // [j][d]

    const int tid  = threadIdx.x;
    const int lane = tid & 31, warp = tid >> 5;
    const int g = lane >> 2, tig = lane & 3;
    const int wm = (warp >> 1) * 64;       // i
    const int wn = (warp & 1) * 32;        // d
    const int gz = blockIdx.y;
    const int i0 = blockIdx.x * 128;
    const float* sbase = g_s + (long long)gz * 512 * 512;
    const float* vbase = g_v + gz * SEQ * 64;

    float acc[4][4][4];
    #pragma unroll
    for (int a = 0; a < 4; a++)
        #pragma unroll
        for (int b = 0; b < 4; b++)
            #pragma unroll
            for (int c = 0; c < 4; c++) acc[a][b][c] = 0.f;

    for (int jt = 0; jt < 32; jt++) {
        const int j0 = jt * 16;
        #pragma unroll
        for (int q = 0; q < 4; q++) {
            int idx = q * 128 + tid;              // 0..511
            int row = idx >> 2;                   // 0..127 (i)
            int jg  = (idx & 3) * 4;
            float4 pv4 = *(const float4*)&sbase[(i0 + row) * 512 + j0 + jg];
            float h, l;
            split1(pv4.x, h, l); PsH[jg + 0][row] = h; PsL[jg + 0][row] = l;
            split1(pv4.y, h, l); PsH[jg + 1][row] = h; PsL[jg + 1][row] = l;
            split1(pv4.z, h, l); PsH[jg + 2][row] = h; PsL[jg + 2][row] = l;
            split1(pv4.w, h, l); PsH[jg + 3][row] = h; PsL[jg + 3][row] = l;
        }
        #pragma unroll
        for (int q = 0; q < 2; q++) {
            int idx = q * 128 + tid;              // 0..255
            int row = idx >> 4;                   // 0..15 (j)
            int d4  = (idx & 15) * 4;
            float4 vv = *(const float4*)&vbase[(j0 + row) * 64 + d4];
            float4 vh, vl;
            split1(vv.x, vh.x, vl.x); split1(vv.y, vh.y, vl.y);
            split1(vv.z, vh.z, vl.z); split1(vv.w, vh.w, vl.w);
            *(float4*)&VsH[row][d4] = vh;
            *(float4*)&VsL[row][d4] = vl;
        }
        __syncthreads();
        MMA3_CHUNK(&PsH[0][0], &PsL[0][0], 132, &VsH[0][0], &VsL[0][0], 68);
        __syncthreads();
    }

    #pragma unroll
    for (int mt = 0; mt < 4; mt++) {
        #pragma unroll
        for (int r = 0; r < 2; r++) {
            int i = i0 + wm + mt * 16 + g + r * 8;
            float* orow = &g_ow[(gz * 512 + i) * 64];
            #pragma unroll
            for (int nt = 0; nt < 4; nt++) {
                int d = wn + nt * 8 + 2 * tig;
                *(float2*)&orow[d] = make_float2(acc[mt][nt][r * 2],
                                                 acc[mt][nt][r * 2 + 1]);
            }
        }
    }
}

// ============================================================================
// Kernel 5: window layout [g][i][d] -> pixel layout [ch][p] via SMEM staging.
// ============================================================================
__global__ void __launch_bounds__(256) transpose_kernel()
{
    __shared__ __align__(16) float T[128][68];

    const int tid = threadIdx.x;
    const int g  = blockIdx.y;
    const int i0 = blockIdx.x * 128;
    const float* src = g_ow + (g * 512 + i0) * 64;

    #pragma unroll
    for (int q = 0; q < 8; q++) {
        int idx = q * 256 + tid;       // 0..2047
        int row = idx >> 4;            // 0..127
        int d4  = (idx & 15) * 4;
        *(float4*)&T[row][d4] = *(const float4*)&src[row * 64 + d4];
    }
    __syncthreads();

    const int head = g >> 6;
    const int win  = g & 63;
    const int wxv  = win >> 3, wyv = win & 7;

    #pragma unroll
    for (int q = 0; q < 2; q++) {
        int t   = q * 256 + tid;       // 0..511
        int d   = t & 63;
        int run = t >> 6;              // 0..7
        int ib  = run * 16;
        int ig  = i0 + ib;
        int f   = ig >> 8;
        int w1  = (ig >> 4) & 15;
        int pbase = f * 16384 + (wxv * 16 + w1) * 128 + wyv * 16;
        float* dst = g_op + (head * 64 + d) * NP + pbase;
        #pragma unroll
        for (int e = 0; e < 4; e++) {
            float4 v4;
            v4.x = T[ib + e * 4 + 0][d];
            v4.y = T[ib + e * 4 + 1][d];
            v4.z = T[ib + e * 4 + 2][d];
            v4.w = T[ib + e * 4 + 3][d];
            *(float4*)&dst[e * 4] = v4;
        }
    }
}

// ============================================================================
// Kernel 6: final projection + bias. Block 128o(M) x 128p(N).
// M = o so stores stay coalesced along p (n-adjacent).
// ============================================================================
__global__ void __launch_bounds__(256) out_kernel(
    const float* __restrict__ wo,
    const float* __restrict__ bo,
    float* __restrict__ out)
{
    __shared__ __align__(16) float BsH[16][132], BsL[16][132];   // [c][p]
    __shared__ __align__(16) float WsH[16][132], WsL[16][132];   // [c][o]

    const int tid  = threadIdx.x;
    const int lane = tid & 31, warp = tid >> 5;
    const int g = lane >> 2, tig = lane & 3;
    const int wm = (warp >> 2) * 64;       // o
    const int wn = (warp & 3) * 32;        // p
    const int p0 = blockIdx.x * 128;
    const int o0 = blockIdx.y * 128;

    float acc[4][4][4];
    #pragma unroll
    for (int a = 0; a < 4; a++)
        #pragma unroll
        for (int b = 0; b < 4; b++)
            #pragma unroll
            for (int c = 0; c < 4; c++) acc[a][b][c] = 0.f;

    for (int kt = 0; kt < 32; kt++) {
        const int c0 = kt * 16;
        #pragma unroll
        for (int q = 0; q < 2; q++) {
            int idx = q * 256 + tid;
            int xr = idx >> 5;
            int xc = (idx & 31) * 4;
            float4 xv = *(const float4*)&g_op[(c0 + xr) * NP + p0 + xc];
            float4 xh, xl;
            split1(xv.x, xh.x, xl.x); split1(xv.y, xh.y, xl.y);
            split1(xv.z, xh.z, xl.z); split1(xv.w, xh.w, xl.w);
            *(float4*)&BsH[xr][xc] = xh;
            *(float4*)&BsL[xr][xc] = xl;

            int orow = idx >> 2;
            int cg   = (idx & 3) * 4;
            float4 w = *(const float4*)&wo[(o0 + orow) * 512 + c0 + cg];
            float h, l;
            split1(w.x, h, l); WsH[cg + 0][orow] = h; WsL[cg + 0][orow] = l;
            split1(w.y, h, l); WsH[cg + 1][orow] = h; WsL[cg + 1][orow] = l;
            split1(w.z, h, l); WsH[cg + 2][orow] = h; WsL[cg + 2][orow] = l;
            split1(w.w, h, l); WsH[cg + 3][orow] = h; WsL[cg + 3][orow] = l;
        }
        __syncthreads();
        // A-side = W [c][o] (M = o), B-side = data [c][p] (N = p)
        MMA3_CHUNK(&WsH[0][0], &WsL[0][0], 132, &BsH[0][0], &BsL[0][0], 132);
        __syncthreads();
    }

    #pragma unroll
    for (int mt = 0; mt < 4; mt++) {
        int o  = o0 + wm + mt * 16 + g;
        float b0 = bo[o];
        float b1 = bo[o + 8];
        #pragma unroll
        for (int nt = 0; nt < 4; nt++) {
            int p = p0 + wn + nt * 8 + 2 * tig;
            *(float2*)&out[o * NP + p] =
                make_float2(acc[mt][nt][0] + b0, acc[mt][nt][1] + b0);
            *(float2*)&out[(o + 8) * NP + p] =
                make_float2(acc[mt][nt][2] + b1, acc[mt][nt][3] + b1);
        }
    }
}

// ============================================================================
extern "C" void kernel_launch(void* const* d_in, const int* in_sizes, int n_in,
                              void* d_out, int out_size)
{
    const float* x   = (const float*)d_in[0];
    const float* wq  = (const float*)d_in[1];
    const float* wkv = (const float*)d_in[2];
    const float* wo  = (const float*)d_in[3];
    const float* bo  = (const float*)d_in[4];
    float* out = (float*)d_out;

    proj_kernel     <<<dim3(NP / 128, 1536 / 128), 256>>>(x, wq, wkv);
    qk_kernel       <<<dim3(4, 4, NG),             256>>>();
    softmax_kernel  <<<dim3(NG * SEQ / 8),         256>>>();
    pv_kernel       <<<dim3(4, NG),                128>>>();
    transpose_kernel<<<dim3(4, NG),                256>>>();
    out_kernel      <<<dim3(NP / 128, 256 / 128),  256>>>(wo, bo, out);
}

// round 5
// speedup vs baseline: 1.2955x; 1.1106x over previous
#include <cuda_runtime.h>

#define NP 32768          // pixels = F*H*W = 2*128*128
#define SEQ 512           // window sequence length
#define NG 512            // head*window groups = 8*64

// ---------------- scratch (static __device__; no allocation APIs) ----------
__device__ float g_q [NG * SEQ * 64];          // [g][i][d]
__device__ float g_k [NG * SEQ * 64];          // [g][j][d]
__device__ float g_v [NG * SEQ * 64];          // [g][j][d]
__device__ float g_s [NG * SEQ * SEQ];         // [g][i][j]
__device__ float g_ow[NG * SEQ * 64];          // attn out, window layout
__device__ float g_op[512 * NP];               // attn out, pixel layout [ch][p]

// ---------------- tf32 helpers ---------------------------------------------
__device__ __forceinline__ float totf32(float x) {
    float r; asm("cvt.rna.tf32.f32 %0, %1;" : "=f"(r) : "f"(x)); return r;
}
#define SPLITU(v, H, L)                                                       \
    { float _h = totf32(v); (H) = __float_as_uint(_h);                        \
      (L) = __float_as_uint(totf32((v) - _h)); }

__device__ __forceinline__ void mma_tf32(float* d, const unsigned* a, const unsigned* b) {
    asm("mma.sync.aligned.m16n8k8.row.col.f32.tf32.tf32.f32 "
        "{%0,%1,%2,%3}, {%4,%5,%6,%7}, {%8,%9}, {%0,%1,%2,%3};"
        : "+f"(d[0]), "+f"(d[1]), "+f"(d[2]), "+f"(d[3])
        : "r"(a[0]), "r"(a[1]), "r"(a[2]), "r"(a[3]), "r"(b[0]), "r"(b[1]));
}

// tf32x3 over one k=32 SMEM chunk (4 k8 steps), warp tile 64(M) x 32(N).
// Raw fp32 in SMEM; hi/lo split in registers. 3-pass MMA ordering for ILP.
// AP/BP: lane pointer expressions (use mt/nt, k0, g, tig, wm, wn).
// AO1: +8 rows of M;  AO2: +4 of K;  BO1: +4 of K.
#define MMA3_K32(AP, AO1, AO2, BP, BO1)                                       \
    _Pragma("unroll")                                                         \
    for (int ks = 0; ks < 4; ks++) {                                          \
        const int k0 = ks * 8;                                                \
        unsigned ah[4][4], al[4][4], bh[4][2], bl[4][2];                      \
        _Pragma("unroll")                                                     \
        for (int mt = 0; mt < 4; mt++) {                                      \
            const float* _p = (AP);                                           \
            float _r0 = _p[0], _r1 = _p[(AO1)], _r2 = _p[(AO2)];              \
            float _r3 = _p[(AO1) + (AO2)];                                    \
            SPLITU(_r0, ah[mt][0], al[mt][0]);                                \
            SPLITU(_r1, ah[mt][1], al[mt][1]);                                \
            SPLITU(_r2, ah[mt][2], al[mt][2]);                                \
            SPLITU(_r3, ah[mt][3], al[mt][3]);                                \
        }                                                                     \
        _Pragma("unroll")                                                     \
        for (int nt = 0; nt < 4; nt++) {                                      \
            const float* _q = (BP);                                           \
            float _s0 = _q[0], _s1 = _q[(BO1)];                               \
            SPLITU(_s0, bh[nt][0], bl[nt][0]);                                \
            SPLITU(_s1, bh[nt][1], bl[nt][1]);                                \
        }                                                                     \
        _Pragma("unroll")                                                     \
        for (int nt = 0; nt < 4; nt++)                                        \
            _Pragma("unroll")                                                 \
            for (int mt = 0; mt < 4; mt++)                                    \
                mma_tf32(acc[mt][nt], al[mt], bh[nt]);                        \
        _Pragma("unroll")                                                     \
        for (int nt = 0; nt < 4; nt++)                                        \
            _Pragma("unroll")                                                 \
            for (int mt = 0; mt < 4; mt++)                                    \
                mma_tf32(acc[mt][nt], ah[mt], bl[nt]);                        \
        _Pragma("unroll")                                                     \
        for (int nt = 0; nt < 4; nt++)                                        \
            _Pragma("unroll")                                                 \
            for (int mt = 0; mt < 4; mt++)                                    \
                mma_tf32(acc[mt][nt], ah[mt], bh[nt]);                        \
    }

#define ZERO_ACC()                                                            \
    float acc[4][4][4];                                                       \
    _Pragma("unroll")                                                         \
    for (int a = 0; a < 4; a++)                                               \
        _Pragma("unroll")                                                     \
        for (int b = 0; b < 4; b++)                                           \
            _Pragma("unroll")                                                 \
            for (int c = 0; c < 4; c++) acc[a][b][c] = 0.f;

// ============================================================================
// Kernel 1: QKV projection. out[o][p] = sum_c W[o][c] * x[c][p]
// Block 128p(M) x 128o(N), K chunks of 32. Xs [k][M] s136, Ws [N][k] s36.
// ============================================================================
__global__ void __launch_bounds__(256) proj_kernel(
    const float* __restrict__ x,
    const float* __restrict__ wq,
    const float* __restrict__ wkv)
{
    __shared__ __align__(16) float Xs[32][136];   // [c][p] raw
    __shared__ __align__(16) float Ws[128][36];   // [o][c] raw

    const int tid  = threadIdx.x;
    const int lane = tid & 31, warp = tid >> 5;
    const int g = lane >> 2, tig = lane & 3;
    const int wm = (warp >> 2) * 64;       // p
    const int wn = (warp & 3) * 32;        // o
    const int p0 = blockIdx.x * 128;
    const int o0 = blockIdx.y * 128;

    ZERO_ACC();

    for (int kt = 0; kt < 8; kt++) {
        const int c0 = kt * 32;
        #pragma unroll
        for (int q = 0; q < 4; q++) {
            int idx = q * 256 + tid;              // 0..1023
            int xr = idx >> 5;                    // 0..31
            int xc = (idx & 31) * 4;
            *(float4*)&Xs[xr][xc] = *(const float4*)&x[(c0 + xr) * NP + p0 + xc];
            int orow = idx >> 3;                  // 0..127
            int cg   = (idx & 7) * 4;             // 0..28
            int o    = o0 + orow;
            const float* arow = (o < 512) ? (wq + o * 256) : (wkv + (o - 512) * 256);
            *(float4*)&Ws[orow][cg] = *(const float4*)&arow[c0 + cg];
        }
        __syncthreads();
        MMA3_K32(&Xs[k0 + tig][wm + mt * 16 + g], 8, 544,
                 &Ws[wn + nt * 8 + g][k0 + tig], 4);
        __syncthreads();
    }

    // epilogue: D[m=p][n=o] fragments -> float2 along d into [g][i][d] bufs
    #pragma unroll
    for (int nt = 0; nt < 4; nt++) {
        int o   = o0 + wn + nt * 8 + 2 * tig;
        int sel = o >> 9;
        int oc  = o & 511;
        float* buf = (sel == 0) ? g_q : ((sel == 1) ? g_k : g_v);
        int gd = (oc >> 6) * 64;   // head*64
        int dl = oc & 63;
        #pragma unroll
        for (int mt = 0; mt < 4; mt++) {
            #pragma unroll
            for (int r = 0; r < 2; r++) {
                int p  = p0 + wm + mt * 16 + g + r * 8;
                int f  = p >> 14, hh = (p >> 7) & 127, ww = p & 127;
                int gidx = gd + (hh >> 4) * 8 + (ww >> 4);
                int i    = f * 256 + (hh & 15) * 16 + (ww & 15);
                *(float2*)&buf[(gidx * 512 + i) * 64 + dl] =
                    make_float2(acc[mt][nt][r * 2], acc[mt][nt][r * 2 + 1]);
            }
        }
    }
}

// ============================================================================
// Kernel 2: S = scale * Q @ K^T per group. Block 128i(M) x 128j(N), K=64.
// Qs [M][k] s36, Ks [N][k] s36.
// ============================================================================
__global__ void __launch_bounds__(256) qk_kernel()
{
    __shared__ __align__(16) float Qs[128][36];   // [i][d] raw
    __shared__ __align__(16) float Ks[128][36];   // [j][d] raw

    const int tid  = threadIdx.x;
    const int lane = tid & 31, warp = tid >> 5;
    const int g = lane >> 2, tig = lane & 3;
    const int wm = (warp >> 2) * 64;       // i
    const int wn = (warp & 3) * 32;        // j
    const int gz = blockIdx.z;
    const int i0 = blockIdx.y * 128;
    const int j0 = blockIdx.x * 128;
    const float* qbase = g_q + gz * SEQ * 64;
    const float* kbase = g_k + gz * SEQ * 64;

    ZERO_ACC();

    for (int dcb = 0; dcb < 2; dcb++) {
        const int dc = dcb * 32;
        #pragma unroll
        for (int q = 0; q < 4; q++) {
            int idx = q * 256 + tid;              // 0..1023
            int row = idx >> 3;                   // 0..127
            int dg  = (idx & 7) * 4;
            *(float4*)&Qs[row][dg] = *(const float4*)&qbase[(i0 + row) * 64 + dc + dg];
            *(float4*)&Ks[row][dg] = *(const float4*)&kbase[(j0 + row) * 64 + dc + dg];
        }
        __syncthreads();
        MMA3_K32(&Qs[wm + mt * 16 + g][k0 + tig], 288, 4,
                 &Ks[wn + nt * 8 + g][k0 + tig], 4);
        __syncthreads();
    }

    const float scale = 0.125f;
    #pragma unroll
    for (int mt = 0; mt < 4; mt++) {
        #pragma unroll
        for (int r = 0; r < 2; r++) {
            int i = i0 + wm + mt * 16 + g + r * 8;
            float* srow = &g_s[(gz * 512 + i) * 512 + j0];
            #pragma unroll
            for (int nt = 0; nt < 4; nt++) {
                int jj = wn + nt * 8 + 2 * tig;
                *(float2*)&srow[jj] = make_float2(acc[mt][nt][r * 2] * scale,
                                                  acc[mt][nt][r * 2 + 1] * scale);
            }
        }
    }
}

// ============================================================================
// Kernel 3: row softmax over j (512). One warp per row.
// ============================================================================
__global__ void __launch_bounds__(256) softmax_kernel()
{
    const int warp = threadIdx.x >> 5;
    const int lane = threadIdx.x & 31;
    const long long row = (long long)blockIdx.x * 8 + warp;
    float* rp = g_s + row * 512;

    float4 v[4];
    #pragma unroll
    for (int c = 0; c < 4; c++) v[c] = *(const float4*)&rp[c * 128 + lane * 4];

    float m = -1e30f;
    #pragma unroll
    for (int c = 0; c < 4; c++)
        m = fmaxf(m, fmaxf(fmaxf(v[c].x, v[c].y), fmaxf(v[c].z, v[c].w)));
    #pragma unroll
    for (int s = 16; s > 0; s >>= 1)
        m = fmaxf(m, __shfl_xor_sync(0xffffffffu, m, s));

    float sum = 0.f;
    #pragma unroll
    for (int c = 0; c < 4; c++) {
        v[c].x = __expf(v[c].x - m); v[c].y = __expf(v[c].y - m);
        v[c].z = __expf(v[c].z - m); v[c].w = __expf(v[c].w - m);
        sum += v[c].x + v[c].y + v[c].z + v[c].w;
    }
    #pragma unroll
    for (int s = 16; s > 0; s >>= 1)
        sum += __shfl_xor_sync(0xffffffffu, sum, s);

    const float inv = 1.0f / sum;
    #pragma unroll
    for (int c = 0; c < 4; c++) {
        v[c].x *= inv; v[c].y *= inv; v[c].z *= inv; v[c].w *= inv;
        *(float4*)&rp[c * 128 + lane * 4] = v[c];
    }
}

// ============================================================================
// Kernel 4: O = P @ V per group. Block 128i(M) x 64d(N), 128 threads.
// Ps [M][k] s36, Vs [k][N] s72. K = 512 in chunks of 32.
// ============================================================================
__global__ void __launch_bounds__(128) pv_kernel()
{
    __shared__ __align__(16) float Ps[128][36];   // [i][j] raw
    __shared__ __align__(16) float Vs[32][72];    // [j][d] raw

    const int tid  = threadIdx.x;
    const int lane = tid & 31, warp = tid >> 5;
    const int g = lane >> 2, tig = lane & 3;
    const int wm = (warp >> 1) * 64;       // i
    const int wn = (warp & 1) * 32;        // d
    const int gz = blockIdx.y;
    const int i0 = blockIdx.x * 128;
    const float* sbase = g_s + (long long)gz * 512 * 512;
    const float* vbase = g_v + gz * SEQ * 64;

    ZERO_ACC();

    for (int jt = 0; jt < 16; jt++) {
        const int j0 = jt * 32;
        #pragma unroll
        for (int q = 0; q < 8; q++) {
            int idx = q * 128 + tid;              // 0..1023
            int row = idx >> 3;                   // 0..127 (i)
            int jg  = (idx & 7) * 4;
            *(float4*)&Ps[row][jg] = *(const float4*)&sbase[(i0 + row) * 512 + j0 + jg];
        }
        #pragma unroll
        for (int q = 0; q < 4; q++) {
            int idx = q * 128 + tid;              // 0..511
            int vr  = idx >> 4;                   // 0..31 (j)
            int vd  = (idx & 15) * 4;
            *(float4*)&Vs[vr][vd] = *(const float4*)&vbase[(j0 + vr) * 64 + vd];
        }
        __syncthreads();
        MMA3_K32(&Ps[wm + mt * 16 + g][k0 + tig], 288, 4,
                 &Vs[k0 + tig][wn + nt * 8 + g], 288);
        __syncthreads();
    }

    #pragma unroll
    for (int mt = 0; mt < 4; mt++) {
        #pragma unroll
        for (int r = 0; r < 2; r++) {
            int i = i0 + wm + mt * 16 + g + r * 8;
            float* orow = &g_ow[(gz * 512 + i) * 64];
            #pragma unroll
            for (int nt = 0; nt < 4; nt++) {
                int d = wn + nt * 8 + 2 * tig;
                *(float2*)&orow[d] = make_float2(acc[mt][nt][r * 2],
                                                 acc[mt][nt][r * 2 + 1]);
            }
        }
    }
}

// ============================================================================
// Kernel 5: window layout [g][i][d] -> pixel layout [ch][p] via SMEM staging.
// ============================================================================
__global__ void __launch_bounds__(256) transpose_kernel()
{
    __shared__ __align__(16) float T[128][68];

    const int tid = threadIdx.x;
    const int g  = blockIdx.y;
    const int i0 = blockIdx.x * 128;
    const float* src = g_ow + (g * 512 + i0) * 64;

    #pragma unroll
    for (int q = 0; q < 8; q++) {
        int idx = q * 256 + tid;       // 0..2047
        int row = idx >> 4;            // 0..127
        int d4  = (idx & 15) * 4;
        *(float4*)&T[row][d4] = *(const float4*)&src[row * 64 + d4];
    }
    __syncthreads();

    const int head = g >> 6;
    const int win  = g & 63;
    const int wxv  = win >> 3, wyv = win & 7;

    #pragma unroll
    for (int q = 0; q < 2; q++) {
        int t   = q * 256 + tid;       // 0..511
        int d   = t & 63;
        int run = t >> 6;              // 0..7
        int ib  = run * 16;
        int ig  = i0 + ib;
        int f   = ig >> 8;
        int w1  = (ig >> 4) & 15;
        int pbase = f * 16384 + (wxv * 16 + w1) * 128 + wyv * 16;
        float* dst = g_op + (head * 64 + d) * NP + pbase;
        #pragma unroll
        for (int e = 0; e < 4; e++) {
            float4 v4;
            v4.x = T[ib + e * 4 + 0][d];
            v4.y = T[ib + e * 4 + 1][d];
            v4.z = T[ib + e * 4 + 2][d];
            v4.w = T[ib + e * 4 + 3][d];
            *(float4*)&dst[e * 4] = v4;
        }
    }
}

// ============================================================================
// Kernel 6: final projection + bias. Block 128o(M) x 128p(N), K=512.
// Ws [M][k] s36, Bs [k][N] s136. Stores coalesced along p.
// ============================================================================
__global__ void __launch_bounds__(256) out_kernel(
    const float* __restrict__ wo,
    const float* __restrict__ bo,
    float* __restrict__ out)
{
    __shared__ __align__(16) float Bs[32][136];   // [c][p] raw
    __shared__ __align__(16) float Ws[128][36];   // [o][c] raw

    const int tid  = threadIdx.x;
    const int lane = tid & 31, warp = tid >> 5;
    const int g = lane >> 2, tig = lane & 3;
    const int wm = (warp >> 2) * 64;       // o
    const int wn = (warp & 3) * 32;        // p
    const int p0 = blockIdx.x * 128;
    const int o0 = blockIdx.y * 128;

    ZERO_ACC();

    for (int kt = 0; kt < 16; kt++) {
        const int c0 = kt * 32;
        #pragma unroll
        for (int q = 0; q < 4; q++) {
            int idx = q * 256 + tid;
            int xr = idx >> 5;
            int xc = (idx & 31) * 4;
            *(float4*)&Bs[xr][xc] = *(const float4*)&g_op[(c0 + xr) * NP + p0 + xc];
            int orow = idx >> 3;
            int cg   = (idx & 7) * 4;
            *(float4*)&Ws[orow][cg] = *(const float4*)&wo[(o0 + orow) * 512 + c0 + cg];
        }
        __syncthreads();
        MMA3_K32(&Ws[wm + mt * 16 + g][k0 + tig], 288, 4,
                 &Bs[k0 + tig][wn + nt * 8 + g], 544);
        __syncthreads();
    }

    #pragma unroll
    for (int mt = 0; mt < 4; mt++) {
        int o  = o0 + wm + mt * 16 + g;
        float b0 = bo[o];
        float b1 = bo[o + 8];
        #pragma unroll
        for (int nt = 0; nt < 4; nt++) {
            int p = p0 + wn + nt * 8 + 2 * tig;
            *(float2*)&out[o * NP + p] =
                make_float2(acc[mt][nt][0] + b0, acc[mt][nt][1] + b0);
            *(float2*)&out[(o + 8) * NP + p] =
                make_float2(acc[mt][nt][2] + b1, acc[mt][nt][3] + b1);
        }
    }
}

// ============================================================================
extern "C" void kernel_launch(void* const* d_in, const int* in_sizes, int n_in,
                              void* d_out, int out_size)
{
    const float* x   = (const float*)d_in[0];
    const float* wq  = (const float*)d_in[1];
    const float* wkv = (const float*)d_in[2];
    const float* wo  = (const float*)d_in[3];
    const float* bo  = (const float*)d_in[4];
    float* out = (float*)d_out;

    proj_kernel     <<<dim3(NP / 128, 1536 / 128), 256>>>(x, wq, wkv);
    qk_kernel       <<<dim3(4, 4, NG),             256>>>();
    softmax_kernel  <<<dim3(NG * SEQ / 8),         256>>>();
    pv_kernel       <<<dim3(4, NG),                128>>>();
    transpose_kernel<<<dim3(4, NG),                256>>>();
    out_kernel      <<<dim3(NP / 128, 256 / 128),  256>>>(wo, bo, out);
}